// round 6
// baseline (speedup 1.0000x reference)
#include <cuda_runtime.h>

#define NDAYS  4
#define NHOURS 24
#define NDH    96          // NDAYS*NHOURS
#define NLINKS 2000
#define NPATHS 20000
#define NODS   4000
#define MAXL   64          // max links per path (mean ~10)
#define MAXP   320         // max paths per link (mean ~100)

// ---------------- device scratch ----------------
__device__ float          g_V[NLINKS][NDH];       // V transposed: [link][dh]
__device__ float          g_ev[NPATHS][NDH];      // exp(vf)
__device__ float          g_sc[NODS * NDH];       // sum exp(vf) -> then q^2/denom
__device__ int            g_plc[NPATHS];          // links-per-path counts
__device__ unsigned short g_pl[NPATHS][MAXL];     // CSC: link ids per path
__device__ int            g_lpc[NLINKS];          // paths-per-link counts
__device__ unsigned int   g_lp[NLINKS][MAXP];     // CSR: (od<<15 | path) per link
__device__ int            g_od_start[NODS + 1];

// ---------------- kernel 1: fused setup (counters + V + boundaries + denom=0) ----------------
__global__ void k_setup(const float* __restrict__ X,
                        const float* __restrict__ theta_raw,
                        const float* __restrict__ theta_links,
                        const int*   __restrict__ od_of_path) {
    int i = blockIdx.x * blockDim.x + threadIdx.x;

    if (i < NLINKS) g_lpc[i] = 0;

    if (i < NODS * NDH) g_sc[i] = 0.0f;

    if (i < NPATHS) {
        g_plc[i] = 0;
        int od   = od_of_path[i];
        int prev = (i == 0) ? -1 : od_of_path[i - 1];
        for (int o = prev + 1; o <= od; ++o) g_od_start[o] = i;
        if (i == NPATHS - 1) {
            for (int o = od + 1; o <= NODS; ++o) g_od_start[o] = NPATHS;
        }
    }

    if (i < NDH * NLINKS) {
        int dh = i / NLINKS;
        int l  = i - dh * NLINKS;
        float t0 = fminf(theta_raw[0], 0.0f);
        float t1 = fminf(theta_raw[1], 0.0f);
        float t2 = fminf(theta_raw[2], 0.0f);
        float t3 = fminf(theta_raw[3], 0.0f);
        const float* xp = X + ((size_t)dh * NLINKS + l) * 5;
        g_V[l][dh] = xp[1] * t0 + xp[2] * t1 + xp[3] * t2 + xp[4] * t3 + theta_links[l];
    }
}

// ---------------- kernel 2: scan D (160 MB), build CSC + CSR (od packed) ----------------
__device__ __forceinline__ void sp_append(int l, int p, const int* __restrict__ odp) {
    int c1 = atomicAdd(&g_plc[p], 1);
    if (c1 < MAXL) g_pl[p][c1] = (unsigned short)l;
    int c2 = atomicAdd(&g_lpc[l], 1);
    if (c2 < MAXP) g_lp[l][c2] = ((unsigned)odp[p] << 15) | (unsigned)p;
}

__device__ __forceinline__ void sp_proc(unsigned x, unsigned y, unsigned z, unsigned w,
                                        int i, int pq, const int* __restrict__ odp) {
    if ((x | y | z | w) == 0u) return;
    int l = i / pq;
    int p = (i - l * pq) * 4;
    if (x) sp_append(l, p + 0, odp);
    if (y) sp_append(l, p + 1, odp);
    if (z) sp_append(l, p + 2, odp);
    if (w) sp_append(l, p + 3, odp);
}

__global__ void k_sparse(const uint4* __restrict__ D4,
                         const int*   __restrict__ od_of_path) {
    const int n4 = NLINKS * (NPATHS / 4);   // 10,000,000 uint4s
    const int pq = NPATHS / 4;
    const int nt = n4 / 4;
    int S = gridDim.x * blockDim.x;
    for (int t = blockIdx.x * blockDim.x + threadIdx.x; t < nt; t += S) {
        int j = 4 * t;
        uint4 v0 = __ldcs(&D4[j + 0]);
        uint4 v1 = __ldcs(&D4[j + 1]);
        uint4 v2 = __ldcs(&D4[j + 2]);
        uint4 v3 = __ldcs(&D4[j + 3]);
        unsigned any = v0.x | v0.y | v0.z | v0.w | v1.x | v1.y | v1.z | v1.w |
                       v2.x | v2.y | v2.z | v2.w | v3.x | v3.y | v3.z | v3.w;
        if (any == 0u) continue;
        sp_proc(v0.x, v0.y, v0.z, v0.w, j + 0, pq, od_of_path);
        sp_proc(v1.x, v1.y, v1.z, v1.w, j + 1, pq, od_of_path);
        sp_proc(v2.x, v2.y, v2.z, v2.w, j + 2, pq, od_of_path);
        sp_proc(v3.x, v3.y, v3.z, v3.w, j + 3, pq, od_of_path);
    }
}

// ---------------- kernel 3: vf gather, store exp(vf), accumulate denom ----------------
// No max-subtraction needed: vf in ~[-60, +2], exp(vf) never under/overflows fp32.
__global__ void k_vf(const int* __restrict__ od_of_path) {
    int p  = blockIdx.x * 4 + threadIdx.y;   // block(96,4), grid 5000
    int dh = threadIdx.x;
    int cnt = min(g_plc[p], MAXL);
    const ushort4* pl4 = (const ushort4*)g_pl[p];
    float a0 = 0.f, a1 = 0.f, a2 = 0.f, a3 = 0.f;
    int i = 0;
    for (; i + 4 <= cnt; i += 4) {
        ushort4 l4 = pl4[i >> 2];
        a0 += g_V[l4.x][dh];
        a1 += g_V[l4.y][dh];
        a2 += g_V[l4.z][dh];
        a3 += g_V[l4.w][dh];
    }
    for (; i < cnt; ++i) a0 += g_V[g_pl[p][i]][dh];
    float ev = __expf((a0 + a1) + (a2 + a3));
    g_ev[p][dh] = ev;
    int od = od_of_path[p];
    atomicAdd(&g_sc[od * NDH + dh], ev);   // fire-and-forget RED
}

// ---------------- kernel 4: tiny in-place sc = q^2 / denom ----------------
__global__ void k_sc(const float* __restrict__ q_sqrt) {
    int idx = blockIdx.x * blockDim.x + threadIdx.x;   // NODS*NDH threads
    if (idx >= NODS * NDH) return;
    int od = idx / NDH;
    float qv = q_sqrt[od];
    g_sc[idx] = __fdividef(qv * qv, g_sc[idx]);
}

// ---------------- kernel 5: x = relu(sum ev*sc), BPR epilogue, write out ----------------
__global__ void k_out(const float* __restrict__ X,
                      const float* __restrict__ log_alpha,
                      const float* __restrict__ beta_raw,
                      const float* __restrict__ kcap,
                      float* __restrict__ out) {
    int l  = blockIdx.x * 2 + threadIdx.y;   // block(96,2), grid 1000
    int dh = threadIdx.x;
    int cnt = min(g_lpc[l], MAXP);
    const uint4* lp4 = (const uint4*)g_lp[l];
    float a0 = 0.f, a1 = 0.f, a2 = 0.f, a3 = 0.f;
    int i = 0;
    for (; i + 4 <= cnt; i += 4) {
        uint4 e = lp4[i >> 2];
        int p0 = e.x & 0x7FFF, o0 = e.x >> 15;
        int p1 = e.y & 0x7FFF, o1 = e.y >> 15;
        int p2 = e.z & 0x7FFF, o2 = e.z >> 15;
        int p3 = e.w & 0x7FFF, o3 = e.w >> 15;
        a0 = fmaf(g_ev[p0][dh], g_sc[o0 * NDH + dh], a0);
        a1 = fmaf(g_ev[p1][dh], g_sc[o1 * NDH + dh], a1);
        a2 = fmaf(g_ev[p2][dh], g_sc[o2 * NDH + dh], a2);
        a3 = fmaf(g_ev[p3][dh], g_sc[o3 * NDH + dh], a3);
    }
    for (; i < cnt; ++i) {
        unsigned e = g_lp[l][i];
        int p = e & 0x7FFF, o = e >> 15;
        a0 = fmaf(g_ev[p][dh], g_sc[o * NDH + dh], a0);
    }
    float x = fmaxf((a0 + a1) + (a2 + a3), 0.0f);

    float alpha = __expf(log_alpha[l]);
    float beta  = fminf(fmaxf(beta_raw[l], 1e-12f), 4.0f);
    float tt    = X[((size_t)dh * NLINKS + l) * 5];   // X[...,0]
    float ratio = x / kcap[l];
    out[(size_t)dh * NLINKS + l] = tt * (1.0f + alpha * __powf(ratio, beta));
}

// ---------------- launcher ----------------
extern "C" void kernel_launch(void* const* d_in, const int* in_sizes, int n_in,
                              void* d_out, int out_size) {
    const float* X           = (const float*)d_in[0];
    const float* theta_raw   = (const float*)d_in[1];
    const float* theta_links = (const float*)d_in[2];
    const float* q_sqrt      = (const float*)d_in[3];
    const float* log_alpha   = (const float*)d_in[4];
    const float* beta_raw    = (const float*)d_in[5];
    const float* kcap        = (const float*)d_in[6];
    const float* D           = (const float*)d_in[7];
    const int*   od_of_path  = (const int*)d_in[8];
    float*       out         = (float*)d_out;

    k_setup<<<(NODS * NDH + 255) / 256, 256>>>(X, theta_raw, theta_links, od_of_path);
    k_sparse<<<1216, 256>>>((const uint4*)D, od_of_path);   // one full wave on 152 SMs
    k_vf<<<NPATHS / 4, dim3(NDH, 4)>>>(od_of_path);
    k_sc<<<(NODS * NDH + 255) / 256, 256>>>(q_sqrt);
    k_out<<<NLINKS / 2, dim3(NDH, 2)>>>(X, log_alpha, beta_raw, kcap, out);
}

// round 7
// speedup vs baseline: 1.1706x; 1.1706x over previous
#include <cuda_runtime.h>

#define NDAYS  4
#define NHOURS 24
#define NDH    96          // NDAYS*NHOURS
#define NDH4   24          // NDH/4
#define NLINKS 2000
#define NPATHS 20000
#define NODS   4000
#define MAXL   64          // max links per path (mean ~10)
#define MAXP   320         // max paths per link (mean ~100)

// ---------------- device scratch ----------------
__device__ float          g_V[NLINKS][NDH];       // V transposed: [link][dh]
__device__ float          g_vf[NPATHS][NDH];      // path utilities
__device__ float          g_f[NPATHS][NDH];       // f = pf * q
__device__ float          g_denom[NODS * NDH];    // sum of exp(vf) per (od, dh)
__device__ int            g_plc[NPATHS];          // links-per-path counts
__device__ unsigned short g_pl[NPATHS][MAXL];     // CSC: link ids per path
__device__ int            g_lpc[NLINKS];          // paths-per-link counts
__device__ unsigned short g_lp[NLINKS][MAXP];     // CSR: path ids per link
__device__ int            g_od_start[NODS + 1];   // (unused; kept for layout stability)

// ---------------- kernel 1: fused setup (counters + V + denom=0) ----------------
__global__ void k_setup(const float* __restrict__ X,
                        const float* __restrict__ theta_raw,
                        const float* __restrict__ theta_links) {
    int i = blockIdx.x * blockDim.x + threadIdx.x;

    if (i < NLINKS) g_lpc[i] = 0;
    if (i < NPATHS) g_plc[i] = 0;
    if (i < NODS * NDH) g_denom[i] = 0.0f;

    if (i < NDH * NLINKS) {
        int dh = i / NLINKS;
        int l  = i - dh * NLINKS;
        float t0 = fminf(theta_raw[0], 0.0f);
        float t1 = fminf(theta_raw[1], 0.0f);
        float t2 = fminf(theta_raw[2], 0.0f);
        float t3 = fminf(theta_raw[3], 0.0f);
        const float* xp = X + ((size_t)dh * NLINKS + l) * 5;
        g_V[l][dh] = xp[1] * t0 + xp[2] * t1 + xp[3] * t2 + xp[4] * t3 + theta_links[l];
    }
}

// ---------------- kernel 2: scan D (160 MB), build CSC + CSR ----------------
__device__ __forceinline__ void sp_append(int l, int p) {
    int c1 = atomicAdd(&g_plc[p], 1);
    if (c1 < MAXL) g_pl[p][c1] = (unsigned short)l;
    int c2 = atomicAdd(&g_lpc[l], 1);
    if (c2 < MAXP) g_lp[l][c2] = (unsigned short)p;
}

__device__ __forceinline__ void sp_proc(unsigned x, unsigned y, unsigned z, unsigned w,
                                        int i, int pq) {
    if ((x | y | z | w) == 0u) return;
    int l = i / pq;
    int p = (i - l * pq) * 4;
    if (x) sp_append(l, p + 0);
    if (y) sp_append(l, p + 1);
    if (z) sp_append(l, p + 2);
    if (w) sp_append(l, p + 3);
}

__global__ void k_sparse(const uint4* __restrict__ D4) {
    const int n4 = NLINKS * (NPATHS / 4);   // 10,000,000 uint4s
    const int pq = NPATHS / 4;
    const int nt = n4 / 4;
    int S = gridDim.x * blockDim.x;
    for (int t = blockIdx.x * blockDim.x + threadIdx.x; t < nt; t += S) {
        int j = 4 * t;
        uint4 v0 = __ldcs(&D4[j + 0]);
        uint4 v1 = __ldcs(&D4[j + 1]);
        uint4 v2 = __ldcs(&D4[j + 2]);
        uint4 v3 = __ldcs(&D4[j + 3]);
        unsigned any = v0.x | v0.y | v0.z | v0.w | v1.x | v1.y | v1.z | v1.w |
                       v2.x | v2.y | v2.z | v2.w | v3.x | v3.y | v3.z | v3.w;
        if (any == 0u) continue;
        sp_proc(v0.x, v0.y, v0.z, v0.w, j + 0, pq);
        sp_proc(v1.x, v1.y, v1.z, v1.w, j + 1, pq);
        sp_proc(v2.x, v2.y, v2.z, v2.w, j + 2, pq);
        sp_proc(v3.x, v3.y, v3.z, v3.w, j + 3, pq);
    }
}

// ---------------- kernel 3: vf gather + exp accumulation into denom ----------------
// No max-subtraction needed: vf in ~[-60, +2], exp(vf) never under/overflows fp32.
__global__ void k_vf(const int* __restrict__ od_of_path) {
    int p  = blockIdx.x * 4 + threadIdx.y;   // block(96,4), grid 5000
    int dh = threadIdx.x;
    int cnt = min(g_plc[p], MAXL);
    const ushort4* pl4 = (const ushort4*)g_pl[p];
    float a0 = 0.f, a1 = 0.f, a2 = 0.f, a3 = 0.f;
    int i = 0;
    for (; i + 4 <= cnt; i += 4) {
        ushort4 l4 = pl4[i >> 2];
        a0 += g_V[l4.x][dh];
        a1 += g_V[l4.y][dh];
        a2 += g_V[l4.z][dh];
        a3 += g_V[l4.w][dh];
    }
    for (; i < cnt; ++i) a0 += g_V[g_pl[p][i]][dh];
    float vf = (a0 + a1) + (a2 + a3);
    g_vf[p][dh] = vf;
    int od = od_of_path[p];
    atomicAdd(&g_denom[od * NDH + dh], __expf(vf));   // fire-and-forget RED
}

// ---------------- kernel 4: vectorized f = exp(vf) * q^2 / denom ----------------
// One thread per (path, 4 consecutive dh): float4 loads/stores, 1 od lookup / 16B.
__global__ void k_scale(const float* __restrict__ q_sqrt,
                        const int*   __restrict__ od_of_path) {
    int idx = blockIdx.x * blockDim.x + threadIdx.x;   // NPATHS*NDH4 threads
    if (idx >= NPATHS * NDH4) return;
    int p  = idx / NDH4;
    int c  = (idx - p * NDH4) * 4;
    int od = od_of_path[p];
    float qv = q_sqrt[od];
    qv *= qv;
    float4 d = *(const float4*)&g_denom[od * NDH + c];
    float4 v = *(const float4*)&g_vf[p][c];
    float4 f;
    f.x = __fdividef(__expf(v.x) * qv, d.x);
    f.y = __fdividef(__expf(v.y) * qv, d.y);
    f.z = __fdividef(__expf(v.z) * qv, d.z);
    f.w = __fdividef(__expf(v.w) * qv, d.w);
    *(float4*)&g_f[p][c] = f;
}

// ---------------- kernel 5: x = relu(D f), BPR epilogue, write out ----------------
__global__ void k_out(const float* __restrict__ X,
                      const float* __restrict__ log_alpha,
                      const float* __restrict__ beta_raw,
                      const float* __restrict__ kcap,
                      float* __restrict__ out) {
    int l  = blockIdx.x * 2 + threadIdx.y;   // block(96,2), grid 1000
    int dh = threadIdx.x;
    int cnt = min(g_lpc[l], MAXP);
    const ushort4* lp4 = (const ushort4*)g_lp[l];
    float a0 = 0.f, a1 = 0.f, a2 = 0.f, a3 = 0.f;
    int i = 0;
    for (; i + 4 <= cnt; i += 4) {
        ushort4 p4 = lp4[i >> 2];
        a0 += g_f[p4.x][dh];
        a1 += g_f[p4.y][dh];
        a2 += g_f[p4.z][dh];
        a3 += g_f[p4.w][dh];
    }
    for (; i < cnt; ++i) a0 += g_f[g_lp[l][i]][dh];
    float x = fmaxf((a0 + a1) + (a2 + a3), 0.0f);

    float alpha = __expf(log_alpha[l]);
    float beta  = fminf(fmaxf(beta_raw[l], 1e-12f), 4.0f);
    float tt    = X[((size_t)dh * NLINKS + l) * 5];   // X[...,0]
    float ratio = x / kcap[l];
    out[(size_t)dh * NLINKS + l] = tt * (1.0f + alpha * __powf(ratio, beta));
}

// ---------------- launcher ----------------
extern "C" void kernel_launch(void* const* d_in, const int* in_sizes, int n_in,
                              void* d_out, int out_size) {
    const float* X           = (const float*)d_in[0];
    const float* theta_raw   = (const float*)d_in[1];
    const float* theta_links = (const float*)d_in[2];
    const float* q_sqrt      = (const float*)d_in[3];
    const float* log_alpha   = (const float*)d_in[4];
    const float* beta_raw    = (const float*)d_in[5];
    const float* kcap        = (const float*)d_in[6];
    const float* D           = (const float*)d_in[7];
    const int*   od_of_path  = (const int*)d_in[8];
    float*       out         = (float*)d_out;

    k_setup<<<(NODS * NDH + 255) / 256, 256>>>(X, theta_raw, theta_links);
    k_sparse<<<1216, 256>>>((const uint4*)D);          // one full wave on 152 SMs
    k_vf<<<NPATHS / 4, dim3(NDH, 4)>>>(od_of_path);
    k_scale<<<(NPATHS * NDH4 + 255) / 256, 256>>>(q_sqrt, od_of_path);
    k_out<<<NLINKS / 2, dim3(NDH, 2)>>>(X, log_alpha, beta_raw, kcap, out);
}